// round 5
// baseline (speedup 1.0000x reference)
#include <cuda_runtime.h>
#include <float.h>

#define BB 4
#define DD 64
#define NN 4096
#define KNN 16
#define SPLIT 4
#define TQ 64
#define NCAND (NN / SPLIT) /* 1024 */
#define CC 32
#define KEEP 20
#define SHORT (SPLIT * KEEP) /* 80 */
#define RQW 4                /* refine: warps (queries) per block */
#define EQT 8                /* edge: queries per block */

#define EF_ELEMS ((size_t)BB * 2 * DD * NN * KNN) /* 33,554,432 */

// Scratch (allocation-free rule: __device__ globals)
__device__ float  g_sqn[BB * NN];
__device__ int    g_pidx[BB * SPLIT * NN * KEEP];
__device__ int    g_fidx[BB * NN * KNN];
__device__ float4 g_pcT4[BB * NN * (DD / 4)];   // pcT[b][n][d], float4-aligned

// ---------------------------------------------------------------------------
// Kernel 0: transpose pc[b][d][n] -> pcT[b][n][d]
// ---------------------------------------------------------------------------
__global__ void transpose_kernel(const float* __restrict__ pc) {
    __shared__ float tile[32][33];
    int b  = blockIdx.z;
    int d0 = blockIdx.y * 32;
    int n0 = blockIdx.x * 32;
    int tx = threadIdx.x, ty = threadIdx.y; // 32 x 8
    float* pT = (float*)g_pcT4;
#pragma unroll
    for (int r = 0; r < 4; ++r) {
        int y = ty + r * 8;
        tile[y][tx] = pc[((size_t)b * DD + d0 + y) * NN + n0 + tx];
    }
    __syncthreads();
#pragma unroll
    for (int r = 0; r < 4; ++r) {
        int y = ty + r * 8;
        pT[((size_t)b * NN + n0 + y) * DD + d0 + tx] = tile[tx][y];
    }
}

// ---------------------------------------------------------------------------
// Kernel 1: squared norms — EXACT: one sequential fp32 FMA chain over d
// ascending per point (matches reference reduction bit-for-bit).
// ---------------------------------------------------------------------------
__global__ void sqnorm_kernel(const float* __restrict__ pc) {
    int t = blockIdx.x * blockDim.x + threadIdx.x;
    if (t >= BB * NN) return;
    int b = t / NN, n = t % NN;
    const float* p = pc + (size_t)b * DD * NN + n;
    float s = 0.f;
#pragma unroll
    for (int d = 0; d < DD; ++d) {
        float v = p[(size_t)d * NN];
        s = __fmaf_rn(v, v, s);
    }
    g_sqn[t] = s;
}

// ---------------------------------------------------------------------------
// Approx top-KEEP insertion (ordering only; exact refine fixes ties later)
// ---------------------------------------------------------------------------
__device__ __forceinline__ void insertK(float* bestd, int* besti, float dd, int ii) {
    bool placed = false;
#pragma unroll
    for (int j = KEEP - 1; j >= 1; --j) {
        if (!placed) {
            if (dd < bestd[j - 1]) {
                bestd[j] = bestd[j - 1];
                besti[j] = besti[j - 1];
            } else {
                bestd[j] = dd;
                besti[j] = ii;
                placed = true;
            }
        }
    }
    if (!placed) { bestd[0] = dd; besti[0] = ii; }
}

// ---------------------------------------------------------------------------
// Kernel 2: APPROX partial kNN shortlist. Free FMA ordering (4 accumulators)
// -> pipe-saturating. Keeps top-KEEP candidate indices per (query, split).
// ---------------------------------------------------------------------------
__global__ void __launch_bounds__(TQ) knn_partial(const float* __restrict__ pc) {
    const int qt = blockIdx.x;
    const int b  = blockIdx.y;
    const int sp = blockIdx.z;
    const int q  = qt * TQ + threadIdx.x;

    const float* pcb = pc + (size_t)b * DD * NN;

    float qv[DD];
#pragma unroll
    for (int d = 0; d < DD; ++d) qv[d] = pcb[(size_t)d * NN + q];
    const float sqq = g_sqn[b * NN + q];

    float bestd[KEEP];
    int   besti[KEEP];
#pragma unroll
    for (int k = 0; k < KEEP; ++k) { bestd[k] = FLT_MAX; besti[k] = -1; }

    __shared__ float sc[CC * DD];
    __shared__ float ssq[CC];

    const int c0base = sp * NCAND;

    for (int cc0 = 0; cc0 < NCAND; cc0 += CC) {
        const int c0 = c0base + cc0;
        __syncthreads();
        for (int i = threadIdx.x; i < CC * DD; i += TQ) {
            int d = i / CC;
            int c = i % CC;
            sc[c * DD + d] = pcb[(size_t)d * NN + c0 + c];
        }
        if (threadIdx.x < CC) ssq[threadIdx.x] = g_sqn[b * NN + c0 + threadIdx.x];
        __syncthreads();

#pragma unroll 1
        for (int c = 0; c < CC; ++c) {
            const float4* r0 = (const float4*)&sc[c * DD];
            float a0 = 0.f, a1 = 0.f, a2 = 0.f, a3 = 0.f;
#pragma unroll
            for (int j = 0; j < DD / 4; ++j) {
                float4 x = r0[j];
                a0 = fmaf(qv[4 * j + 0], x.x, a0);
                a1 = fmaf(qv[4 * j + 1], x.y, a1);
                a2 = fmaf(qv[4 * j + 2], x.z, a2);
                a3 = fmaf(qv[4 * j + 3], x.w, a3);
            }
            float d2 = sqq + ssq[c] - 2.f * ((a0 + a1) + (a2 + a3));
            const int ci = c0 + c;
            if (ci != q && d2 < bestd[KEEP - 1]) insertK(bestd, besti, d2, ci);
        }
    }

    const size_t off = (((size_t)b * SPLIT + sp) * NN + q) * KEEP;
#pragma unroll
    for (int k = 0; k < KEEP; ++k) g_pidx[off + k] = besti[k];
}

// ---------------------------------------------------------------------------
// Kernel 3: EXACT refine. One warp per query; recompute the bit-exact
// reference key dist = fp32_sqrt(max((sqq+sqc) - 2*seq_fma_dot, 0)) for the
// SHORT=80 shortlisted candidates; stable top-16 via u64 (dist_bits, idx) min.
// ---------------------------------------------------------------------------
__global__ void __launch_bounds__(RQW * 32) knn_refine(float* __restrict__ out_idx) {
    __shared__ float srow[RQW][32][65];
    __shared__ float squery[RQW][64];

    const int warp = threadIdx.x >> 5;
    const int lane = threadIdx.x & 31;
    const int qg = blockIdx.x * RQW + warp;   // 0 .. B*NN-1
    const int b = qg / NN, n = qg % NN;

    // Load query row (coalesced from pcT) into smem
    if (lane < 16) {
        float4 v = g_pcT4[(size_t)qg * 16 + lane];
        squery[warp][lane * 4 + 0] = v.x;
        squery[warp][lane * 4 + 1] = v.y;
        squery[warp][lane * 4 + 2] = v.z;
        squery[warp][lane * 4 + 3] = v.w;
    }
    const float sqq = g_sqn[qg];

    // Shortlist slots owned by this lane: lane, lane+32, lane+64
    int myidx[3];
#pragma unroll
    for (int r = 0; r < 3; ++r) {
        int slot = lane + 32 * r;
        if (slot < SHORT) {
            int s = slot / KEEP, j = slot % KEEP;
            myidx[r] = g_pidx[(((size_t)b * SPLIT + s) * NN + n) * KEEP + j];
        } else {
            myidx[r] = -1;
        }
    }

    unsigned long long mykey[3];
#pragma unroll
    for (int r = 0; r < 3; ++r) mykey[r] = 0xFFFFFFFFFFFFFFFFull;

    for (int r = 0; r < 3; ++r) {
        __syncwarp();
        // Stage 32 candidate rows (coalesced from pcT) into smem, stride 65
        for (int j = 0; j < 16; ++j) {
            int flat = j * 32 + lane;
            int row = flat >> 4;          // 0..31
            int f4  = flat & 15;
            int c = __shfl_sync(0xffffffffu, myidx[r], row);
            if (c >= 0) {
                float4 v = g_pcT4[((size_t)b * NN + c) * 16 + f4];
                float* dst = &srow[warp][row][f4 * 4];
                dst[0] = v.x; dst[1] = v.y; dst[2] = v.z; dst[3] = v.w;
            }
        }
        __syncwarp();
        int c = myidx[r];
        if (c >= 0) {
            const float* qr = squery[warp];
            const float* cr = srow[warp][lane];
            float acc = 0.f;
#pragma unroll
            for (int d = 0; d < DD; ++d)
                acc = __fmaf_rn(qr[d], cr[d], acc);   // exact sequential chain
            float sqc = g_sqn[b * NN + c];
            float d2  = __fsub_rn(__fadd_rn(sqq, sqc), __fmul_rn(2.0f, acc));
            float di  = __fsqrt_rn(fmaxf(d2, 0.0f));
            mykey[r] = ((unsigned long long)__float_as_uint(di) << 32) | (unsigned)c;
        }
    }

    // Stable top-16: iterative warp-min over u64 keys (dist asc, idx asc)
    for (int i = 0; i < KNN; ++i) {
        unsigned long long k = mykey[0];
        if (mykey[1] < k) k = mykey[1];
        if (mykey[2] < k) k = mykey[2];
#pragma unroll
        for (int off = 16; off > 0; off >>= 1) {
            unsigned long long o = __shfl_xor_sync(0xffffffffu, k, off);
            if (o < k) k = o;
        }
        // winner removes itself (indices unique -> exactly one match)
#pragma unroll
        for (int r = 0; r < 3; ++r)
            if (mykey[r] == k) mykey[r] = 0xFFFFFFFFFFFFFFFFull;
        if (lane == 0) {
            int bi = (int)(unsigned)(k & 0xFFFFFFFFull);
            g_fidx[(size_t)qg * KNN + i]  = bi;
            out_idx[(size_t)qg * KNN + i] = (float)bi;
        }
    }
}

// ---------------------------------------------------------------------------
// Kernel 4: edge features. Gather neighbor rows coalesced from pcT into smem,
// then write both halves coalesced (float4 over k).
// ---------------------------------------------------------------------------
__global__ void __launch_bounds__(256) edge_kernel(float* __restrict__ out) {
    __shared__ float snb[EQT * KNN][65];   // 128 neighbor rows
    __shared__ float scen[EQT][65];        // central rows
    __shared__ int   sidx[EQT * KNN];

    const int b  = blockIdx.y;
    const int n0 = blockIdx.x * EQT;
    const int tid = threadIdx.x;

    if (tid < EQT * KNN)
        sidx[tid] = g_fidx[((size_t)b * NN + n0 + tid / KNN) * KNN + tid % KNN];
    if (tid < EQT * 16) {
        int qq = tid / 16, f4 = tid % 16;
        float4 v = g_pcT4[((size_t)b * NN + n0 + qq) * 16 + f4];
        float* dst = &scen[qq][f4 * 4];
        dst[0] = v.x; dst[1] = v.y; dst[2] = v.z; dst[3] = v.w;
    }
    __syncthreads();

    // Gather 128 neighbor rows x 16 float4, coalesced
#pragma unroll
    for (int it = 0; it < 8; ++it) {
        int flat = it * 256 + tid;
        int row = flat >> 4;      // 0..127
        int f4  = flat & 15;
        int c = sidx[row];
        float4 v = g_pcT4[((size_t)b * NN + c) * 16 + f4];
        float* dst = &snb[row][f4 * 4];
        dst[0] = v.x; dst[1] = v.y; dst[2] = v.z; dst[3] = v.w;
    }
    __syncthreads();

    float4* out4 = (float4*)out;
#pragma unroll
    for (int t = 0; t < 16; ++t) {
        int i  = t * 256 + tid;
        int k4 = i & 3;
        int nn = (i >> 2) & 7;
        int d2 = i >> 5;           // 0..127
        int d  = d2 & 63;
        float cen = scen[nn][d];
        float4 o;
        if (d2 < 64) {
            o = make_float4(cen, cen, cen, cen);
        } else {
            int row = nn * KNN + k4 * 4;
            o.x = snb[row + 0][d] - cen;
            o.y = snb[row + 1][d] - cen;
            o.z = snb[row + 2][d] - cen;
            o.w = snb[row + 3][d] - cen;
        }
        out4[(((size_t)b * 128 + d2) * NN + n0 + nn) * 4 + k4] = o;
    }
}

// ---------------------------------------------------------------------------
extern "C" void kernel_launch(void* const* d_in, const int* in_sizes, int n_in,
                              void* d_out, int out_size) {
    const float* pc = (const float*)d_in[0];
    float* out = (float*)d_out;

    {
        dim3 g(NN / 32, DD / 32, BB), t(32, 8);
        transpose_kernel<<<g, t>>>(pc);
    }
    sqnorm_kernel<<<(BB * NN + 255) / 256, 256>>>(pc);

    {
        dim3 grid(NN / TQ, BB, SPLIT);
        knn_partial<<<grid, TQ>>>(pc);
    }

    knn_refine<<<BB * NN / RQW, RQW * 32>>>(out + EF_ELEMS);

    {
        dim3 g(NN / EQT, BB);
        edge_kernel<<<g, 256>>>(out);
    }
}

// round 6
// speedup vs baseline: 1.2375x; 1.2375x over previous
#include <cuda_runtime.h>
#include <float.h>

#define BB 4
#define DD 64
#define NN 4096
#define KNN 16
#define SPLIT 4
#define TQ 128
#define NCAND (NN / SPLIT) /* 1024 */
#define CC 32
#define CAP 8               /* deferred-insert stack depth per thread */
#define EQT 8               /* edge: queries per block */

#define EF_ELEMS ((size_t)BB * 2 * DD * NN * KNN) /* 33,554,432 */

// Scratch (allocation-free rule: __device__ globals)
__device__ float  g_sqn[BB * NN];
__device__ float  g_pdist[BB * SPLIT * NN * KNN];
__device__ int    g_pidx[BB * SPLIT * NN * KNN];
__device__ int    g_fidx[BB * NN * KNN];
__device__ float4 g_pcT4[BB * NN * (DD / 4)];   // pcT[b][n][d]

// ---------------------------------------------------------------------------
// Kernel 0: transpose pc[b][d][n] -> pcT[b][n][d]  (for edge gather)
// ---------------------------------------------------------------------------
__global__ void transpose_kernel(const float* __restrict__ pc) {
    __shared__ float tile[32][33];
    int b  = blockIdx.z;
    int d0 = blockIdx.y * 32;
    int n0 = blockIdx.x * 32;
    int tx = threadIdx.x, ty = threadIdx.y; // 32 x 8
    float* pT = (float*)g_pcT4;
#pragma unroll
    for (int r = 0; r < 4; ++r) {
        int y = ty + r * 8;
        tile[y][tx] = pc[((size_t)b * DD + d0 + y) * NN + n0 + tx];
    }
    __syncthreads();
#pragma unroll
    for (int r = 0; r < 4; ++r) {
        int y = ty + r * 8;
        pT[((size_t)b * NN + n0 + y) * DD + d0 + tx] = tile[tx][y];
    }
}

// ---------------------------------------------------------------------------
// Kernel 1: squared norms — EXACT sequential fp32 FMA chain over d ascending.
// ---------------------------------------------------------------------------
__global__ void sqnorm_kernel(const float* __restrict__ pc) {
    int t = blockIdx.x * blockDim.x + threadIdx.x;
    if (t >= BB * NN) return;
    int b = t / NN, n = t % NN;
    const float* p = pc + (size_t)b * DD * NN + n;
    float s = 0.f;
#pragma unroll
    for (int d = 0; d < DD; ++d) {
        float v = p[(size_t)d * NN];
        s = __fmaf_rn(v, v, s);
    }
    g_sqn[t] = s;
}

// ---------------------------------------------------------------------------
// Stable insertion into sorted (dist asc, index asc) top-16.
// Equal keys go AFTER existing (candidates scanned in ascending index order).
// ---------------------------------------------------------------------------
__device__ __forceinline__ void insert16(float* bestd, int* besti, float dd, int ii) {
    bool placed = false;
#pragma unroll
    for (int j = KNN - 1; j >= 1; --j) {
        if (!placed) {
            if (dd < bestd[j - 1]) {
                bestd[j] = bestd[j - 1];
                besti[j] = besti[j - 1];
            } else {
                bestd[j] = dd;
                besti[j] = ii;
                placed = true;
            }
        }
    }
    if (!placed) { bestd[0] = dd; besti[0] = ii; }
}

// ---------------------------------------------------------------------------
// Kernel 2: EXACT partial kNN with deferred selection.
// Hot loop: sequential-chain exact dot (2 interleaved candidates for ILP) +
// cheap predicated push to a per-thread smem stack; insertion ladder runs
// once per tile (warp-batched) instead of per candidate.
// Key = fp32 sqrt(max((sqq+sqc) - 2*dot, 0)) — the reference's exact value.
// ---------------------------------------------------------------------------
__global__ void __launch_bounds__(TQ, 4) knn_partial(const float* __restrict__ pc) {
    const int qt = blockIdx.x;
    const int b  = blockIdx.y;
    const int sp = blockIdx.z;
    const int q  = qt * TQ + threadIdx.x;

    const float* pcb = pc + (size_t)b * DD * NN;

    float qv[DD];
#pragma unroll
    for (int d = 0; d < DD; ++d) qv[d] = pcb[(size_t)d * NN + q];
    const float sqq = g_sqn[b * NN + q];

    float bestd[KNN];
    int   besti[KNN];
#pragma unroll
    for (int k = 0; k < KNN; ++k) { bestd[k] = FLT_MAX; besti[k] = -1; }
    float thresh = FLT_MAX;

    __shared__ float sc[CC * DD];
    __shared__ float ssq[CC];
    __shared__ unsigned long long sstk[TQ][CAP];

    unsigned long long* mystk = sstk[threadIdx.x];
    int cnt = 0;

    const int c0base = sp * NCAND;

    for (int cc0 = 0; cc0 < NCAND; cc0 += CC) {
        const int c0 = c0base + cc0;
        __syncthreads();
        for (int i = threadIdx.x; i < CC * DD; i += TQ) {
            int d = i / CC;
            int c = i % CC;
            sc[c * DD + d] = pcb[(size_t)d * NN + c0 + c];
        }
        if (threadIdx.x < CC) ssq[threadIdx.x] = g_sqn[b * NN + c0 + threadIdx.x];
        __syncthreads();

#pragma unroll 1
        for (int c = 0; c < CC; c += 2) {
            const float4* r0 = (const float4*)&sc[c * DD];
            const float4* r1 = (const float4*)&sc[(c + 1) * DD];
            float a0 = 0.f, a1 = 0.f;   // two independent exact chains
#pragma unroll
            for (int j = 0; j < DD / 4; ++j) {
                float4 x = r0[j];
                float4 y = r1[j];
                a0 = __fmaf_rn(qv[4 * j + 0], x.x, a0);
                a0 = __fmaf_rn(qv[4 * j + 1], x.y, a0);
                a0 = __fmaf_rn(qv[4 * j + 2], x.z, a0);
                a0 = __fmaf_rn(qv[4 * j + 3], x.w, a0);
                a1 = __fmaf_rn(qv[4 * j + 0], y.x, a1);
                a1 = __fmaf_rn(qv[4 * j + 1], y.y, a1);
                a1 = __fmaf_rn(qv[4 * j + 2], y.z, a1);
                a1 = __fmaf_rn(qv[4 * j + 3], y.w, a1);
            }
            float d20 = __fsub_rn(__fadd_rn(sqq, ssq[c]),     __fmul_rn(2.0f, a0));
            float d21 = __fsub_rn(__fadd_rn(sqq, ssq[c + 1]), __fmul_rn(2.0f, a1));
            float di0 = __fsqrt_rn(fmaxf(d20, 0.0f));
            float di1 = __fsqrt_rn(fmaxf(d21, 0.0f));
            const int ci0 = c0 + c, ci1 = c0 + c + 1;

            if (ci0 != q && di0 < thresh) {
                mystk[cnt++] = ((unsigned long long)__float_as_uint(di0) << 32) | (unsigned)ci0;
                if (cnt == CAP) {   // overflow drain (warm-up tiles only)
                    for (int e = 0; e < CAP; ++e) {
                        unsigned long long pk = mystk[e];
                        insert16(bestd, besti, __uint_as_float((unsigned)(pk >> 32)),
                                 (int)(unsigned)(pk & 0xFFFFFFFFull));
                    }
                    cnt = 0;
                    thresh = bestd[KNN - 1];
                }
            }
            if (ci1 != q && di1 < thresh) {
                mystk[cnt++] = ((unsigned long long)__float_as_uint(di1) << 32) | (unsigned)ci1;
                if (cnt == CAP) {
                    for (int e = 0; e < CAP; ++e) {
                        unsigned long long pk = mystk[e];
                        insert16(bestd, besti, __uint_as_float((unsigned)(pk >> 32)),
                                 (int)(unsigned)(pk & 0xFFFFFFFFull));
                    }
                    cnt = 0;
                    thresh = bestd[KNN - 1];
                }
            }
        }

        // warp-batched drain: once per tile
        if (cnt) {
            for (int e = 0; e < cnt; ++e) {
                unsigned long long pk = mystk[e];
                insert16(bestd, besti, __uint_as_float((unsigned)(pk >> 32)),
                         (int)(unsigned)(pk & 0xFFFFFFFFull));
            }
            cnt = 0;
            thresh = bestd[KNN - 1];
        }
    }

    const size_t off = (((size_t)b * SPLIT + sp) * NN + q) * KNN;
#pragma unroll
    for (int k = 0; k < KNN; ++k) {
        g_pdist[off + k] = bestd[k];
        g_pidx[off + k]  = besti[k];
    }
}

// ---------------------------------------------------------------------------
// Kernel 3: merge SPLIT partial sorted lists -> final top-16, index-stable.
// Scan order (split asc, rank asc) == candidate-index order for equal keys.
// ---------------------------------------------------------------------------
__global__ void knn_merge(float* __restrict__ out_idx) {
    int t = blockIdx.x * blockDim.x + threadIdx.x;
    if (t >= BB * NN) return;
    int b = t / NN, n = t % NN;

    float dloc[SPLIT * KNN];
    int   iloc[SPLIT * KNN];
#pragma unroll
    for (int s = 0; s < SPLIT; ++s) {
        size_t off = (((size_t)b * SPLIT + s) * NN + n) * KNN;
#pragma unroll
        for (int k = 0; k < KNN; ++k) {
            dloc[s * KNN + k] = g_pdist[off + k];
            iloc[s * KNN + k] = g_pidx[off + k];
        }
    }
    size_t obase = (size_t)t * KNN;
    for (int k = 0; k < KNN; ++k) {
        float bd = dloc[0];
        int   bp = 0;
        for (int j = 1; j < SPLIT * KNN; ++j) {
            if (dloc[j] < bd) { bd = dloc[j]; bp = j; }
        }
        int bi = iloc[bp];
        dloc[bp] = FLT_MAX;
        g_fidx[obase + k]  = bi;
        out_idx[obase + k] = (float)bi;
    }
}

// ---------------------------------------------------------------------------
// Kernel 4: edge features. Gather neighbor rows coalesced from pcT into smem,
// then write both halves coalesced (float4 over k).
// ---------------------------------------------------------------------------
__global__ void __launch_bounds__(256) edge_kernel(float* __restrict__ out) {
    __shared__ float snb[EQT * KNN][65];
    __shared__ float scen[EQT][65];
    __shared__ int   sidx[EQT * KNN];

    const int b  = blockIdx.y;
    const int n0 = blockIdx.x * EQT;
    const int tid = threadIdx.x;

    if (tid < EQT * KNN)
        sidx[tid] = g_fidx[((size_t)b * NN + n0 + tid / KNN) * KNN + tid % KNN];
    if (tid < EQT * 16) {
        int qq = tid / 16, f4 = tid % 16;
        float4 v = g_pcT4[((size_t)b * NN + n0 + qq) * 16 + f4];
        float* dst = &scen[qq][f4 * 4];
        dst[0] = v.x; dst[1] = v.y; dst[2] = v.z; dst[3] = v.w;
    }
    __syncthreads();

#pragma unroll
    for (int it = 0; it < 8; ++it) {
        int flat = it * 256 + tid;
        int row = flat >> 4;      // 0..127
        int f4  = flat & 15;
        int c = sidx[row];
        float4 v = g_pcT4[((size_t)b * NN + c) * 16 + f4];
        float* dst = &snb[row][f4 * 4];
        dst[0] = v.x; dst[1] = v.y; dst[2] = v.z; dst[3] = v.w;
    }
    __syncthreads();

    float4* out4 = (float4*)out;
#pragma unroll
    for (int t = 0; t < 16; ++t) {
        int i  = t * 256 + tid;
        int k4 = i & 3;
        int nn = (i >> 2) & 7;
        int d2 = i >> 5;           // 0..127
        int d  = d2 & 63;
        float cen = scen[nn][d];
        float4 o;
        if (d2 < 64) {
            o = make_float4(cen, cen, cen, cen);
        } else {
            int row = nn * KNN + k4 * 4;
            o.x = snb[row + 0][d] - cen;
            o.y = snb[row + 1][d] - cen;
            o.z = snb[row + 2][d] - cen;
            o.w = snb[row + 3][d] - cen;
        }
        out4[(((size_t)b * 128 + d2) * NN + n0 + nn) * 4 + k4] = o;
    }
}

// ---------------------------------------------------------------------------
extern "C" void kernel_launch(void* const* d_in, const int* in_sizes, int n_in,
                              void* d_out, int out_size) {
    const float* pc = (const float*)d_in[0];
    float* out = (float*)d_out;

    {
        dim3 g(NN / 32, DD / 32, BB), t(32, 8);
        transpose_kernel<<<g, t>>>(pc);
    }
    sqnorm_kernel<<<(BB * NN + 255) / 256, 256>>>(pc);

    {
        dim3 grid(NN / TQ, BB, SPLIT);
        knn_partial<<<grid, TQ>>>(pc);
    }

    knn_merge<<<(BB * NN + 255) / 256, 256>>>(out + EF_ELEMS);

    {
        dim3 g(NN / EQT, BB);
        edge_kernel<<<g, 256>>>(out);
    }
}